// round 4
// baseline (speedup 1.0000x reference)
#include <cuda_runtime.h>
#include <cuda_bf16.h>
#include <cstdint>

// ---------------- constants ----------------
#define NROWS   8192
#define NHALF   4096
#define DIM     128
#define NT      64            // 128-row tiles
#define NTILES  2080          // upper triangle incl diag
#define SQRT_L2T 1.6986436f   // sqrt(2/ln2); (s*a)·(s*b) = (2/ln2)*sim -> ex2 direct

// dynamic smem: A tile @0 (32KB), B tile @32768 (32KB)
#define SM_A 0
#define SM_B 32768
#define SM_TOTAL 65536

// ---------------- device scratch ----------------
__device__ __nv_bfloat16 g_repsb[NROWS * DIM];  // normalized * SQRT_L2T
__device__ float         g_posT[NHALF];
__device__ float         g_partial[NROWS * NT]; // [row][other-tile], each slot written once
__device__ float         g_blocksum[1024];

// ---------------- helpers ----------------
__device__ __forceinline__ float ex2f(float x) {
    float y; asm("ex2.approx.f32 %0, %1;" : "=f"(y) : "f"(x)); return y;
}
__device__ __forceinline__ uint32_t smem_u32(const void* p) {
    uint32_t a;
    asm("{ .reg .u64 t; cvta.to.shared.u64 t, %1; cvt.u32.u64 %0, t; }" : "=r"(a) : "l"(p));
    return a;
}
__device__ __forceinline__ void ldsm4(uint32_t* r, uint32_t addr) {
    asm volatile("ldmatrix.sync.aligned.m8n8.x4.shared.b16 {%0,%1,%2,%3}, [%4];"
        : "=r"(r[0]), "=r"(r[1]), "=r"(r[2]), "=r"(r[3]) : "r"(addr));
}
__device__ __forceinline__ void mma16816(float* c, const uint32_t* a, uint32_t b0, uint32_t b1) {
    asm volatile(
        "mma.sync.aligned.m16n8k16.row.col.f32.bf16.bf16.f32 "
        "{%0,%1,%2,%3}, {%4,%5,%6,%7}, {%8,%9}, {%0,%1,%2,%3};\n"
        : "+f"(c[0]), "+f"(c[1]), "+f"(c[2]), "+f"(c[3])
        : "r"(a[0]), "r"(a[1]), "r"(a[2]), "r"(a[3]), "r"(b0), "r"(b1));
}
// swizzled byte offset of (row, 16B-chunk) in a 128x256B tile: chunk ^ (row&7)
__device__ __forceinline__ uint32_t sw_off(int r, int c16) {
    return (uint32_t)r * 256 + (uint32_t)(c16 ^ (r & 7)) * 16;
}

// ---------------- kernel 1: fused normalize + positives ----------------
__global__ void normpos_kernel(const float* __restrict__ p1, const float* __restrict__ p2) {
    int i    = blockIdx.x * 8 + (threadIdx.x >> 5);
    int lane = threadIdx.x & 31;
    float4 a = ((const float4*)(p1 + (size_t)i * DIM))[lane];
    float4 b = ((const float4*)(p2 + (size_t)i * DIM))[lane];
    float sa  = a.x * a.x + a.y * a.y + a.z * a.z + a.w * a.w;
    float sb  = b.x * b.x + b.y * b.y + b.z * b.z + b.w * b.w;
    float sab = a.x * b.x + a.y * b.y + a.z * b.z + a.w * b.w;
#pragma unroll
    for (int o = 16; o > 0; o >>= 1) {
        sa  += __shfl_xor_sync(0xffffffffu, sa, o);
        sb  += __shfl_xor_sync(0xffffffffu, sb, o);
        sab += __shfl_xor_sync(0xffffffffu, sab, o);
    }
    float na = fmaxf(sqrtf(sa), 1e-12f), nb = fmaxf(sqrtf(sb), 1e-12f);
    float ia = SQRT_L2T / na, ib = SQRT_L2T / nb;
    if (lane == 0) g_posT[i] = 2.0f * sab / (na * nb);
    __nv_bfloat162 a0 = __floats2bfloat162_rn(a.x * ia, a.y * ia);
    __nv_bfloat162 a1 = __floats2bfloat162_rn(a.z * ia, a.w * ia);
    __nv_bfloat162 b0 = __floats2bfloat162_rn(b.x * ib, b.y * ib);
    __nv_bfloat162 b1 = __floats2bfloat162_rn(b.z * ib, b.w * ib);
    uint2 ua, ub;
    ua.x = *(uint32_t*)&a0; ua.y = *(uint32_t*)&a1;
    ub.x = *(uint32_t*)&b0; ub.y = *(uint32_t*)&b1;
    ((uint2*)(g_repsb + (size_t)i * DIM))[lane] = ua;
    ((uint2*)(g_repsb + (size_t)(i + NHALF) * DIM))[lane] = ub;
}

// ---------------- kernel 2: HMMA tile + exp + row/col sums ----------------
// 2080 CTAs (one upper-triangle 128x128 tile), 256 threads (8 warps, 4 wm x 2 wn).
__global__ __launch_bounds__(256, 2) void sim_kernel() {
    extern __shared__ char smc[];
    uint32_t smem = smem_u32(smc);
    __shared__ float rowpart[2][128];
    __shared__ float colpart[4][128];

    int tid  = threadIdx.x;
    int warp = tid >> 5, lane = tid & 31;
    int wm = warp >> 1, wn = warp & 1;
    int gid = lane >> 2, t4 = lane & 3;

    // decode upper-triangle pair (ti <= tj)
    int b = blockIdx.x;
    int ti = (int)((129.0f - sqrtf(16641.0f - 8.0f * (float)b)) * 0.5f);
#define FROW(t) ((t) * NT - (t) * ((t) - 1) / 2)
    while (FROW(ti + 1) <= b) ti++;
    while (FROW(ti) > b) ti--;
    int tj = ti + (b - FROW(ti));
    int i0 = ti * 128, j0 = tj * 128;
    bool isdiag = (ti == tj);

    // load tiles: coalesced LDG.128, XOR-swizzled STS.128
    {
        const uint4* ga = (const uint4*)(g_repsb + (size_t)i0 * DIM);
#pragma unroll
        for (int it = 0; it < 8; it++) {
            int idx = tid + it * 256;               // 0..2047
            int r = idx >> 4, c16 = idx & 15;
            *(uint4*)(smc + SM_A + sw_off(r, c16)) = ga[idx];
        }
        if (!isdiag) {
            const uint4* gb = (const uint4*)(g_repsb + (size_t)j0 * DIM);
#pragma unroll
            for (int it = 0; it < 8; it++) {
                int idx = tid + it * 256;
                int r = idx >> 4, c16 = idx & 15;
                *(uint4*)(smc + SM_B + sw_off(r, c16)) = gb[idx];
            }
        }
    }
    __syncthreads();
    uint32_t smB = smem + (isdiag ? SM_A : SM_B);

    // ldmatrix bases: lanes 0-15 -> rows 0-15 chunk s=0, lanes 16-31 -> chunk s=1
    // chunk(k,s) = (2k+s)^rx = ((k^(rx>>1))<<1) | (s^(rx&1))
    int rl = lane & 15, s = lane >> 4;
    uint32_t baseA[2], baseB[4];
    int kxA[2], kxB[4];
#pragma unroll
    for (int mf = 0; mf < 2; mf++) {
        int row = wm * 32 + mf * 16 + rl;
        int rx = row & 7;
        baseA[mf] = smem + SM_A + (uint32_t)row * 256 + (uint32_t)(s ^ (rx & 1)) * 16;
        kxA[mf] = rx >> 1;
    }
#pragma unroll
    for (int np = 0; np < 4; np++) {
        int row = wn * 64 + np * 16 + rl;
        int rx = row & 7;
        baseB[np] = smB + (uint32_t)row * 256 + (uint32_t)(s ^ (rx & 1)) * 16;
        kxB[np] = rx >> 1;
    }

    float acc[2][8][4];
#pragma unroll
    for (int mf = 0; mf < 2; mf++)
#pragma unroll
        for (int nf = 0; nf < 8; nf++)
#pragma unroll
            for (int q = 0; q < 4; q++) acc[mf][nf][q] = 0.f;

#pragma unroll
    for (int k = 0; k < 8; k++) {
        uint32_t a[2][4], bf[4][4];
#pragma unroll
        for (int mf = 0; mf < 2; mf++)
            ldsm4(a[mf], baseA[mf] + (uint32_t)((k ^ kxA[mf]) << 5));
#pragma unroll
        for (int np = 0; np < 4; np++)
            ldsm4(bf[np], baseB[np] + (uint32_t)((k ^ kxB[np]) << 5));
#pragma unroll
        for (int nf = 0; nf < 8; nf++) {
            uint32_t b0 = bf[nf >> 1][nf & 1];
            uint32_t b1 = bf[nf >> 1][(nf & 1) + 2];
#pragma unroll
            for (int mf = 0; mf < 2; mf++)
                mma16816(acc[mf][nf], a[mf], b0, b1);
        }
    }

    // epilogue: exp (scale pre-folded), diag masked; row + col sums
    float rs[2][2] = {{0.f, 0.f}, {0.f, 0.f}};
    float cs[8][2];
#pragma unroll
    for (int nf = 0; nf < 8; nf++) { cs[nf][0] = 0.f; cs[nf][1] = 0.f; }

#pragma unroll
    for (int mf = 0; mf < 2; mf++)
#pragma unroll
        for (int h = 0; h < 2; h++) {
            int rowg = i0 + wm * 32 + mf * 16 + h * 8 + gid;
            float ssum = 0.f;
#pragma unroll
            for (int nf = 0; nf < 8; nf++) {
                int colg = j0 + wn * 64 + nf * 8 + t4 * 2;
                float e0 = ex2f(acc[mf][nf][h * 2]);
                float e1 = ex2f(acc[mf][nf][h * 2 + 1]);
                if (isdiag) {
                    if (rowg == colg)     e0 = 0.f;
                    if (rowg == colg + 1) e1 = 0.f;
                }
                ssum += e0 + e1;
                cs[nf][0] += e0;
                cs[nf][1] += e1;
            }
            rs[mf][h] += ssum;
        }

    // row sums: quad-reduce, per-wn halves into smem
#pragma unroll
    for (int mf = 0; mf < 2; mf++)
#pragma unroll
        for (int h = 0; h < 2; h++) {
            float v = rs[mf][h];
            v += __shfl_xor_sync(0xffffffffu, v, 1);
            v += __shfl_xor_sync(0xffffffffu, v, 2);
            if (t4 == 0)
                rowpart[wn][wm * 32 + mf * 16 + h * 8 + gid] = v;
        }

    // col sums (off-diag only): reduce across gid lanes
    if (!isdiag) {
#pragma unroll
        for (int nf = 0; nf < 8; nf++)
#pragma unroll
            for (int c = 0; c < 2; c++) {
                float u = cs[nf][c];
                u += __shfl_xor_sync(0xffffffffu, u, 4);
                u += __shfl_xor_sync(0xffffffffu, u, 8);
                u += __shfl_xor_sync(0xffffffffu, u, 16);
                if (gid == 0)
                    colpart[wm][wn * 64 + nf * 8 + t4 * 2 + c] = u;
            }
    }
    __syncthreads();

    if (tid < 128) {
        float rv = rowpart[0][tid] + rowpart[1][tid];
        g_partial[(size_t)(i0 + tid) * NT + tj] = rv;
        if (!isdiag) {
            float cv = colpart[0][tid] + colpart[1][tid] + colpart[2][tid] + colpart[3][tid];
            g_partial[(size_t)(j0 + tid) * NT + ti] = cv;
        }
    }
}

// ---------------- kernel 3: per-row log-sum (warp per row, coalesced) ----------------
__global__ void finalize1_kernel() {
    __shared__ float part[8];
    int w = threadIdx.x >> 5, lane = threadIdx.x & 31;
    int r = blockIdx.x * 8 + w;
    float2 v = ((const float2*)(g_partial + (size_t)r * NT))[lane];
    float d = v.x + v.y;
#pragma unroll
    for (int o = 16; o > 0; o >>= 1) d += __shfl_xor_sync(0xffffffffu, d, o);
    if (lane == 0) part[w] = logf(d) - g_posT[r & (NHALF - 1)];
    __syncthreads();
    if (threadIdx.x == 0) {
        float ssum = 0.f;
#pragma unroll
        for (int k = 0; k < 8; k++) ssum += part[k];
        g_blocksum[blockIdx.x] = ssum;
    }
}

// ---------------- kernel 4: final scalar ----------------
__global__ void finalize2_kernel(float* __restrict__ out) {
    __shared__ float red[256];
    int t = threadIdx.x;
    red[t] = g_blocksum[t] + g_blocksum[t + 256] + g_blocksum[t + 512] + g_blocksum[t + 768];
    __syncthreads();
    for (int sft = 128; sft > 0; sft >>= 1) {
        if (t < sft) red[t] += red[t + sft];
        __syncthreads();
    }
    if (t == 0) out[0] = red[0] / (float)NROWS;
}

// ---------------- launch ----------------
extern "C" void kernel_launch(void* const* d_in, const int* in_sizes, int n_in,
                              void* d_out, int out_size) {
    const float* p1 = (const float*)d_in[0];
    const float* p2 = (const float*)d_in[1];
    float* out = (float*)d_out;

    cudaFuncSetAttribute(sim_kernel, cudaFuncAttributeMaxDynamicSharedMemorySize, SM_TOTAL);

    normpos_kernel<<<NHALF / 8, 256>>>(p1, p2);
    sim_kernel<<<NTILES, 256, SM_TOTAL>>>();
    finalize1_kernel<<<NROWS / 8, 256>>>();
    finalize2_kernel<<<1, 256>>>(out);
}